// round 13
// baseline (speedup 1.0000x reference)
#include <cuda_runtime.h>
#include <stdint.h>
#include <float.h>

#define TOKENS 16384
#define DIM    256
#define KW     8192
#define KP     64            // packed int32 words per row (256 dims / 4)

#define BM     128
#define BN     128
#define BKW    32            // k'-words per stage (= 128 dims)
#define SPLIT  16
#define NRANGE (KW / SPLIT)              // 512 codes per CTA
#define NCHUNK (NRANGE / BN)             // 4
#define STAGES (NCHUNK * (KP / BKW))     // 8
#define SWI    128                        // smem row width (ints)
#define TILEB  (BKW * SWI * 4)            // 16384 B
#define BUFB   (2 * TILEB)                // 32768
#define NBUF   3
#define SMEM_BYTES (NBUF * BUFB)          // 98304 -> 2 CTAs/SM

#define WWIN   4.5f

// ---------------- device scratch ----------------
__device__ unsigned g_mx[2];              // maxabs bits: [0]=x, [1]=w
__device__ float g_wn[KW];
__device__ float g_pval[TOKENS * SPLIT];
__device__ float g_pval2[TOKENS * SPLIT];
__device__ int   g_pidx[TOKENS * SPLIT];
__device__ int   g_flag[TOKENS];
__device__ int   g_xq[(size_t)KP * TOKENS];   // [k'][token] packed int8x4
__device__ int   g_wq[(size_t)KP * KW];       // [k'][code]

// ---------------- helpers ----------------
__device__ __forceinline__ uint32_t smem_u32(const void* p) {
    uint32_t a;
    asm("{ .reg .u64 t; cvta.to.shared.u64 t, %1; cvt.u32.u64 %0, t; }" : "=r"(a) : "l"(p));
    return a;
}
#define CP_ASYNC16(dst, src) \
    asm volatile("cp.async.cg.shared.global [%0], [%1], 16;" :: "r"(dst), "l"(src) : "memory")

__device__ __forceinline__ void top2_ins(float s, int n, float& v1, int& i1, float& v2) {
    if (s > v1 || (s == v1 && n < i1)) { v2 = v1; v1 = s; i1 = n; }
    else if (s > v2) v2 = s;
}
__device__ __forceinline__ void top2_mrg(float ov1, int oi1, float ov2,
                                         float& v1, int& i1, float& v2) {
    if (ov1 > v1 || (ov1 == v1 && oi1 < i1)) { v2 = fmaxf(v1, ov2); v1 = ov1; i1 = oi1; }
    else v2 = fmaxf(v2, ov1);
}

// ---------------- prepass ----------------
__global__ void init_kernel() {
    if (threadIdx.x < 2) g_mx[threadIdx.x] = 0u;
}

// blocks [0,4096): x float4s; [4096,6144): w float4s
__global__ void maxabs_kernel(const float* __restrict__ x, const float* __restrict__ w) {
    const int b = blockIdx.x;
    float4 v;
    int which;
    if (b < 4096) { v = ((const float4*)x)[b * 256 + threadIdx.x]; which = 0; }
    else          { v = ((const float4*)w)[(b - 4096) * 256 + threadIdx.x]; which = 1; }
    float m = fmaxf(fmaxf(fabsf(v.x), fabsf(v.y)), fmaxf(fabsf(v.z), fabsf(v.w)));
#pragma unroll
    for (int off = 16; off >= 1; off >>= 1)
        m = fmaxf(m, __shfl_xor_sync(0xffffffffu, m, off));
    if ((threadIdx.x & 31) == 0)
        atomicMax(&g_mx[which], __float_as_uint(m));
}

// quantize + pack + transpose: blocks [0, 512): x (32 tokens each); [512, 768): w
__global__ __launch_bounds__(256) void quant_kernel(const float* __restrict__ x,
                                                    const float* __restrict__ w) {
    __shared__ int tile[32 * KP];   // [token-in-tile][k']
    const int b = blockIdx.x;
    const int tid = threadIdx.x;
    const float* src;
    int* dst;
    int width, t0;
    float inv;
    if (b < 512) { src = x; dst = g_xq; width = TOKENS; t0 = b * 32;
                   inv = 127.f / __uint_as_float(g_mx[0]); }
    else         { src = w; dst = g_wq; width = KW; t0 = (b - 512) * 32;
                   inv = 127.f / __uint_as_float(g_mx[1]); }
#pragma unroll
    for (int i = 0; i < 8; i++) {
        const int idx = tid + 256 * i;            // 0..2047
        const int tt = idx >> 6, kk = idx & 63;
        const float4 v = *(const float4*)(src + (size_t)(t0 + tt) * DIM + kk * 4);
        const int q0 = __float2int_rn(v.x * inv);
        const int q1 = __float2int_rn(v.y * inv);
        const int q2 = __float2int_rn(v.z * inv);
        const int q3 = __float2int_rn(v.w * inv);
        tile[tt * KP + kk] = (q0 & 255) | ((q1 & 255) << 8) | ((q2 & 255) << 16) | ((q3 & 255) << 24);
    }
    __syncthreads();
#pragma unroll
    for (int i = 0; i < 8; i++) {
        const int idx = tid + 256 * i;
        const int kk = idx >> 5, tt = idx & 31;
        dst[(size_t)kk * width + t0 + tt] = tile[tt * KP + kk];
    }
}

__global__ void wnorm_kernel(const float* __restrict__ w) {
    int k = blockIdx.x * 256 + threadIdx.x;
    const float4* row = (const float4*)(w + (size_t)k * DIM);
    float s = 0.f;
#pragma unroll
    for (int i = 0; i < DIM / 4; i++) {
        float4 v = row[i];
        s += v.x * v.x + v.y * v.y + v.z * v.z + v.w * v.w;
    }
    g_wn[k] = s;
}

// ---------------- main dp4a kernel ----------------
// grid (TOKENS/BM, SPLIT) = (128, 16); block 256
// tx = tid&15 (8 codes tx+16j), ty = tid>>4 (8 tokens ty*8+p)
extern __shared__ char dynsmem[];

__device__ __forceinline__ void load_stage(uint32_t sbase, int gs, int tid,
                                           int mbase, int nbase0) {
    if (gs < STAGES) {
        const int buf = gs % NBUF;
        const int dt = (gs & 1) * BKW;
        const int nb = nbase0 + (gs >> 1) * BN;
        const uint32_t xb = sbase + buf * BUFB;
        const uint32_t wb = xb + TILEB;
#pragma unroll
        for (int i = 0; i < 4; i++) {
            const int idx = tid + 256 * i;        // 0..1023
            const int row = idx >> 5, col = idx & 31;
            CP_ASYNC16(xb + row * (SWI * 4) + col * 16,
                       g_xq + (size_t)(dt + row) * TOKENS + mbase + col * 4);
            CP_ASYNC16(wb + row * (SWI * 4) + col * 16,
                       g_wq + (size_t)(dt + row) * KW + nb + col * 4);
        }
    }
    asm volatile("cp.async.commit_group;" ::: "memory");
}

__global__ __launch_bounds__(256, 2)
void vq_dp4a_kernel() {
    char* sm = dynsmem;
    const uint32_t sbase = smem_u32(sm);
    const int tid = threadIdx.x;
    const int tx = tid & 15;
    const int ty = tid >> 4;
    const int mbase = blockIdx.x * BM;
    const int nbase0 = blockIdx.y * NRANGE;

    const float mx = __uint_as_float(g_mx[0]);
    const float mw = __uint_as_float(g_mx[1]);
    const float s2 = 2.f * (mx * mw) / (127.f * 127.f);

    int acc[8][8];
#pragma unroll
    for (int p = 0; p < 8; p++)
#pragma unroll
        for (int j = 0; j < 8; j++) acc[p][j] = 0;

    float bv[8], bv2[8];
    int   bi[8];
#pragma unroll
    for (int t = 0; t < 8; t++) { bv[t] = -FLT_MAX; bv2[t] = -FLT_MAX; bi[t] = 0x7fffffff; }

    load_stage(sbase, 0, tid, mbase, nbase0);

    for (int gs = 0; gs < STAGES; gs++) {
        load_stage(sbase, gs + 1, tid, mbase, nbase0);
        asm volatile("cp.async.wait_group 1;" ::: "memory");
        __syncthreads();

        const int* xsp = (const int*)(sm + (gs % NBUF) * BUFB);
        const int* wsp = (const int*)(sm + (gs % NBUF) * BUFB + TILEB);

#pragma unroll
        for (int k = 0; k < BKW; k++) {
            const int4* xrow = (const int4*)(xsp + k * SWI + ty * 8);
            const int4 xa = xrow[0];
            const int4 xb = xrow[1];
#pragma unroll
            for (int j = 0; j < 8; j++) {
                const int wv = wsp[k * SWI + tx + 16 * j];
                acc[0][j] = __dp4a(xa.x, wv, acc[0][j]);
                acc[1][j] = __dp4a(xa.y, wv, acc[1][j]);
                acc[2][j] = __dp4a(xa.z, wv, acc[2][j]);
                acc[3][j] = __dp4a(xa.w, wv, acc[3][j]);
                acc[4][j] = __dp4a(xb.x, wv, acc[4][j]);
                acc[5][j] = __dp4a(xb.y, wv, acc[5][j]);
                acc[6][j] = __dp4a(xb.z, wv, acc[6][j]);
                acc[7][j] = __dp4a(xb.w, wv, acc[7][j]);
            }
        }

        if (gs & 1) {
            // chunk epilogue: score = ||w||^2 - s2*dot_int ; streaming top-2
            const int nb = nbase0 + (gs >> 1) * BN;
#pragma unroll
            for (int j = 0; j < 8; j++) {
                const int n = nb + tx + 16 * j;
                const float wn = __ldg(&g_wn[n]);
#pragma unroll
                for (int p = 0; p < 8; p++) {
                    const float sc = wn - s2 * (float)acc[p][j];
                    top2_ins(sc, n, bv[p], bi[p], bv2[p]);
                    acc[p][j] = 0;
                }
            }
        }
    }

    // reduce across 16 tx lanes (xor within 16-lane halves; ty preserved)
#pragma unroll
    for (int off = 8; off >= 1; off >>= 1) {
#pragma unroll
        for (int t = 0; t < 8; t++) {
            float ov1 = __shfl_xor_sync(0xffffffffu, bv[t], off);
            int   oi1 = __shfl_xor_sync(0xffffffffu, bi[t], off);
            float ov2 = __shfl_xor_sync(0xffffffffu, bv2[t], off);
            top2_mrg(ov1, oi1, ov2, bv[t], bi[t], bv2[t]);
        }
    }

    if (tx == 0) {
        const int s = blockIdx.y;
#pragma unroll
        for (int t = 0; t < 8; t++) {
            const int tok = mbase + ty * 8 + t;
            g_pval[tok * SPLIT + s]  = bv[t];
            g_pidx[tok * SPLIT + s]  = bi[t];
            g_pval2[tok * SPLIT + s] = bv2[t];
        }
    }
}

// ---------------- verify candidates exactly + gather ----------------
__global__ __launch_bounds__(64)
void reduce_gather_kernel(const float* __restrict__ x, const float* __restrict__ wt,
                          float* __restrict__ out) {
    __shared__ float sv1[16], sv2[16];
    __shared__ int   si1[16];
    __shared__ float xs[DIM];
    __shared__ float sred[2];
    __shared__ float sgtop;

    const int tok = blockIdx.x;
    const int tid = threadIdx.x;
    if (tid < 16) {
        sv1[tid] = g_pval[tok * SPLIT + tid];
        sv2[tid] = g_pval2[tok * SPLIT + tid];
        si1[tid] = g_pidx[tok * SPLIT + tid];
    }
    *(float4*)(xs + tid * 4) = *(const float4*)(x + (size_t)tok * DIM + tid * 4);
    __syncthreads();
    if (tid == 0) {
        float g = -FLT_MAX;
#pragma unroll
        for (int s = 0; s < 16; s++) g = fmaxf(g, sv1[s]);
        sgtop = g;
    }
    __syncthreads();
    const float thr = sgtop - WWIN;

    bool scan = false;
    float best = -FLT_MAX;
    int   bidx = 0x7fffffff;
#pragma unroll
    for (int s = 0; s < 16; s++) {
        if (sv2[s] > thr) scan = true;
        if (sv1[s] > thr) {          // uniform across block (smem value)
            const int n = si1[s];
            const float* wr = wt + (size_t)n * DIM;
            float p = 0.f;
#pragma unroll
            for (int q = 0; q < 4; q++) p += xs[tid * 4 + q] * wr[tid * 4 + q];
#pragma unroll
            for (int off = 16; off >= 1; off >>= 1)
                p += __shfl_xor_sync(0xffffffffu, p, off);
            if ((tid & 31) == 0) sred[tid >> 5] = p;
            __syncthreads();
            const float sc = __ldg(&g_wn[n]) - 2.f * (sred[0] + sred[1]);
            if (sc > best || (sc == best && n < bidx)) { best = sc; bidx = n; }
            __syncthreads();
        }
    }
    if (tid == 0) g_flag[tok] = scan ? 1 : 0;
    if (!scan)
        *(float4*)(out + (size_t)tok * DIM + tid * 4) =
            *(const float4*)(wt + (size_t)bidx * DIM + tid * 4);
}

// ---------------- exact fp32 full rescan for flagged tokens ----------------
__global__ __launch_bounds__(256)
void rescue_kernel(const float* __restrict__ x, const float* __restrict__ wt,
                   float* __restrict__ out) {
    const int tok = blockIdx.x;
    if (!g_flag[tok]) return;

    __shared__ float xs[DIM];
    __shared__ float rv[8];
    __shared__ int   ri[8];
    __shared__ int   widx;

    const int tid = threadIdx.x;
    if (tid < DIM / 4)
        *(float4*)(xs + tid * 4) = *(const float4*)(x + (size_t)tok * DIM + tid * 4);
    __syncthreads();

    float bv = -FLT_MAX;
    int   bi = 0x7fffffff;
    for (int n = tid; n < KW; n += 256) {
        const float* wr = wt + (size_t)n * DIM;
        float d = 0.f;
#pragma unroll
        for (int c = 0; c < DIM / 4; c++) {
            const float4 wv = __ldg((const float4*)(wr + c * 4));
            const float4 xv = *(const float4*)(xs + c * 4);
            d += xv.x * wv.x + xv.y * wv.y + xv.z * wv.z + xv.w * wv.w;
        }
        const float sc = __ldg(&g_wn[n]) - 2.f * d;
        if (sc > bv || (sc == bv && n < bi)) { bv = sc; bi = n; }
    }
#pragma unroll
    for (int off = 16; off >= 1; off >>= 1) {
        float ov = __shfl_xor_sync(0xffffffffu, bv, off);
        int   oi = __shfl_xor_sync(0xffffffffu, bi, off);
        if (ov > bv || (ov == bv && oi < bi)) { bv = ov; bi = oi; }
    }
    if ((tid & 31) == 0) { rv[tid >> 5] = bv; ri[tid >> 5] = bi; }
    __syncthreads();
    if (tid == 0) {
        float v = rv[0]; int i = ri[0];
#pragma unroll
        for (int wg = 1; wg < 8; wg++)
            if (rv[wg] > v || (rv[wg] == v && ri[wg] < i)) { v = rv[wg]; i = ri[wg]; }
        widx = i;
    }
    __syncthreads();
    const int sel = widx;
    if (tid < DIM / 4) {
        const float4 v = *(const float4*)(wt + (size_t)sel * DIM + tid * 4);
        *(float4*)(out + (size_t)tok * DIM + tid * 4) = v;
    }
}

// ---------------- launch ----------------
extern "C" void kernel_launch(void* const* d_in, const int* in_sizes, int n_in,
                              void* d_out, int out_size) {
    const float* x  = (const float*)d_in[0];   // [16384, 256]
    const float* wt = (const float*)d_in[1];   // [8192, 256]
    float* out = (float*)d_out;

    cudaFuncSetAttribute(vq_dp4a_kernel, cudaFuncAttributeMaxDynamicSharedMemorySize, SMEM_BYTES);

    init_kernel<<<1, 32>>>();
    maxabs_kernel<<<6144, 256>>>(x, wt);
    quant_kernel<<<768, 256>>>(x, wt);
    wnorm_kernel<<<KW / 256, 256>>>(wt);

    dim3 grid(TOKENS / BM, SPLIT);
    vq_dp4a_kernel<<<grid, 256, SMEM_BYTES>>>();

    reduce_gather_kernel<<<TOKENS, 64>>>(x, wt, out);
    rescue_kernel<<<TOKENS, 256>>>(x, wt, out);
}

// round 14
// speedup vs baseline: 1.5470x; 1.5470x over previous
#include <cuda_runtime.h>
#include <stdint.h>

typedef unsigned long long ull;

#define TOKENS 16384
#define DIM    256
#define KW     8192

#define BM     128
#define BN     128
#define BK     32
#define SPLIT  16
#define NRANGE (KW / SPLIT)             // 512 codes per CTA
#define STAGES ((NRANGE / BN) * (DIM / BK))   // 4 * 8 = 32
#define XROW   256                       // x-dup row width (floats) = 2*BM
#define WROW   128                       // w row width (floats) = BN
#define XTILEB (BK * XROW * 4)           // 32768
#define WTILEB (BK * WROW * 4)           // 16384
#define BUFB   (XTILEB + WTILEB)         // 49152
#define NBUF   2
#define SMEM_BYTES (NBUF * BUFB)         // 98304 -> 2 CTAs/SM

__device__ float g_wn[KW];
__device__ float g_pval[TOKENS * SPLIT];
__device__ int   g_pidx[TOKENS * SPLIT];
__device__ float g_xT2[(size_t)DIM * 2 * TOKENS];  // [d][2*token], x duplicated pairs
__device__ float g_wT[(size_t)DIM * KW];           // [d][code]

// ---------------- helpers ----------------
__device__ __forceinline__ uint32_t smem_u32(const void* p) {
    uint32_t a;
    asm("{ .reg .u64 t; cvta.to.shared.u64 t, %1; cvt.u32.u64 %0, t; }" : "=r"(a) : "l"(p));
    return a;
}
#define CP_ASYNC16(dst, src) \
    asm volatile("cp.async.cg.shared.global [%0], [%1], 16;" :: "r"(dst), "l"(src) : "memory")

// ---------------- prepass ----------------
// w transpose: [KW][256] -> [256][KW]
__global__ void transpose_kernel(const float* __restrict__ src, float* __restrict__ dst,
                                 int rows) {
    __shared__ float t[32][33];
    const int c0 = blockIdx.x * 32;
    const int r0 = blockIdx.y * 32;
#pragma unroll
    for (int i = 0; i < 4; i++)
        t[threadIdx.y + 8 * i][threadIdx.x] =
            src[(size_t)(r0 + threadIdx.y + 8 * i) * DIM + c0 + threadIdx.x];
    __syncthreads();
#pragma unroll
    for (int i = 0; i < 4; i++)
        dst[(size_t)(c0 + threadIdx.y + 8 * i) * rows + r0 + threadIdx.x] =
            t[threadIdx.x][threadIdx.y + 8 * i];
}

// x dup-transpose: [TOKENS][256] -> [256][2*TOKENS], x[t][d] at [d][2t] and [d][2t+1]
__global__ void dup_transpose_kernel(const float* __restrict__ src, float* __restrict__ dst) {
    __shared__ float t[32][33];
    const int c0 = blockIdx.x * 32;   // dim
    const int r0 = blockIdx.y * 32;   // token
#pragma unroll
    for (int i = 0; i < 4; i++)
        t[threadIdx.y + 8 * i][threadIdx.x] =
            src[(size_t)(r0 + threadIdx.y + 8 * i) * DIM + c0 + threadIdx.x];
    __syncthreads();
#pragma unroll
    for (int i = 0; i < 4; i++) {
        const int d = c0 + threadIdx.y + 8 * i;
        const int tk = r0 + threadIdx.x;
        const float v = t[threadIdx.x][threadIdx.y + 8 * i];
        *(float2*)(dst + (size_t)d * (2 * TOKENS) + 2 * tk) = make_float2(v, v);
    }
}

__global__ void wnorm_kernel(const float* __restrict__ w) {
    int k = blockIdx.x * 256 + threadIdx.x;
    const float4* row = (const float4*)(w + (size_t)k * DIM);
    float s = 0.f;
#pragma unroll
    for (int i = 0; i < DIM / 4; i++) {
        float4 v = row[i];
        s += v.x * v.x + v.y * v.y + v.z * v.z + v.w * v.w;
    }
    g_wn[k] = s;
}

// ---------------- main FFMA2 kernel ----------------
// grid (TOKENS/BM, SPLIT) = (128, 16); block 256
// tx = tid&15, ty = tid>>4 (8 tokens: ty*8..+7)
// thread tile: 8 tokens x 4 code-pairs (codes 2*(tx+16jj), +1) = 32 packed accs
extern __shared__ char dynsmem[];

__device__ __forceinline__ void load_stage(uint32_t sbase, int gs, int tid,
                                           int mbase, int nbase0) {
    const int buf = gs & 1;
    const int dt = (gs & 7) * BK;
    const int nb = nbase0 + (gs >> 3) * BN;
    const uint32_t xb = sbase + buf * BUFB;
    const uint32_t wb = xb + XTILEB;
    // x-dup tile: 32 rows x 1024B = 2048 chunks -> 8/thread
#pragma unroll
    for (int i = 0; i < 8; i++) {
        const int idx = tid + 256 * i;
        const int row = idx >> 6, col = idx & 63;
        CP_ASYNC16(xb + row * (XROW * 4) + col * 16,
                   g_xT2 + (size_t)(dt + row) * (2 * TOKENS) + 2 * mbase + col * 4);
    }
    // w tile: 32 rows x 512B = 1024 chunks -> 4/thread
#pragma unroll
    for (int i = 0; i < 4; i++) {
        const int idx = tid + 256 * i;
        const int row = idx >> 5, col = idx & 31;
        CP_ASYNC16(wb + row * (WROW * 4) + col * 16,
                   g_wT + (size_t)(dt + row) * KW + nb + col * 4);
    }
    asm volatile("cp.async.commit_group;" ::: "memory");
}

__global__ __launch_bounds__(256, 2)
void vq_ffma_kernel() {
    char* sm = dynsmem;
    const uint32_t sbase = smem_u32(sm);
    const int tid = threadIdx.x;
    const int tx = tid & 15;
    const int ty = tid >> 4;
    const int mbase = blockIdx.x * BM;
    const int nbase0 = blockIdx.y * NRANGE;

    ull acc[8][4];
#pragma unroll
    for (int p = 0; p < 8; p++)
#pragma unroll
        for (int j = 0; j < 4; j++) acc[p][j] = 0ull;

    float bv[8];
    int   bi[8];
#pragma unroll
    for (int t = 0; t < 8; t++) { bv[t] = -3.402823e38f; bi[t] = 0x7fffffff; }

    load_stage(sbase, 0, tid, mbase, nbase0);

    for (int gs = 0; gs < STAGES; gs++) {
        if (gs + 1 < STAGES)
            load_stage(sbase, gs + 1, tid, mbase, nbase0);   // buf (gs+1)&1 freed in iter gs-1
        else
            asm volatile("cp.async.commit_group;" ::: "memory");
        asm volatile("cp.async.wait_group 1;" ::: "memory"); // stage gs resident
        __syncthreads();

        const float* xsp = (const float*)(sm + (gs & 1) * BUFB);
        const float* wsp = (const float*)(sm + (gs & 1) * BUFB + XTILEB);

#pragma unroll
        for (int k = 0; k < BK; k++) {
            const ulonglong2* xrow = (const ulonglong2*)(xsp + k * XROW + ty * 16);
            ulonglong2 xq0 = xrow[0];   // tokens (0,0),(1,1)
            ulonglong2 xq1 = xrow[1];   // tokens (2,2),(3,3)
            ulonglong2 xq2 = xrow[2];
            ulonglong2 xq3 = xrow[3];
            const ull* wrow = (const ull*)(wsp + k * WROW);
            ull w2[4];
#pragma unroll
            for (int j = 0; j < 4; j++) w2[j] = wrow[tx + 16 * j];  // codes (2c, 2c+1)
#pragma unroll
            for (int j = 0; j < 4; j++) {
                asm("fma.rn.f32x2 %0, %1, %2, %0;" : "+l"(acc[0][j]) : "l"(xq0.x), "l"(w2[j]));
                asm("fma.rn.f32x2 %0, %1, %2, %0;" : "+l"(acc[1][j]) : "l"(xq0.y), "l"(w2[j]));
                asm("fma.rn.f32x2 %0, %1, %2, %0;" : "+l"(acc[2][j]) : "l"(xq1.x), "l"(w2[j]));
                asm("fma.rn.f32x2 %0, %1, %2, %0;" : "+l"(acc[3][j]) : "l"(xq1.y), "l"(w2[j]));
                asm("fma.rn.f32x2 %0, %1, %2, %0;" : "+l"(acc[4][j]) : "l"(xq2.x), "l"(w2[j]));
                asm("fma.rn.f32x2 %0, %1, %2, %0;" : "+l"(acc[5][j]) : "l"(xq2.y), "l"(w2[j]));
                asm("fma.rn.f32x2 %0, %1, %2, %0;" : "+l"(acc[6][j]) : "l"(xq3.x), "l"(w2[j]));
                asm("fma.rn.f32x2 %0, %1, %2, %0;" : "+l"(acc[7][j]) : "l"(xq3.y), "l"(w2[j]));
            }
        }
        __syncthreads();   // buf gs&1 fully consumed before iter gs+1 overwrites it

        if ((gs & 7) == 7) {
            // chunk epilogue: scores for code pair (n, n+1); streaming argmax
            const int nb = nbase0 + (gs >> 3) * BN;
#pragma unroll
            for (int j = 0; j < 4; j++) {
                const int n = nb + 2 * (tx + 16 * j);
                const float wn0 = __ldg(&g_wn[n]);
                const float wn1 = __ldg(&g_wn[n + 1]);
#pragma unroll
                for (int p = 0; p < 8; p++) {
                    float lo, hi;
                    asm("mov.b64 {%0, %1}, %2;" : "=f"(lo), "=f"(hi) : "l"(acc[p][j]));
                    const float s0 = wn0 - 2.f * lo;   // code n
                    const float s1 = wn1 - 2.f * hi;   // code n+1
                    if (s0 > bv[p] || (s0 == bv[p] && n < bi[p])) { bv[p] = s0; bi[p] = n; }
                    if (s1 > bv[p]) { bv[p] = s1; bi[p] = n + 1; }   // strict > keeps smaller idx on tie
                    acc[p][j] = 0ull;
                }
            }
        }
    }

    // reduce across the 16 tx lanes (xor within 16-lane halves; ty preserved)
#pragma unroll
    for (int off = 8; off >= 1; off >>= 1) {
#pragma unroll
        for (int t = 0; t < 8; t++) {
            float ov = __shfl_xor_sync(0xffffffffu, bv[t], off);
            int   oi = __shfl_xor_sync(0xffffffffu, bi[t], off);
            if (ov > bv[t] || (ov == bv[t] && oi < bi[t])) { bv[t] = ov; bi[t] = oi; }
        }
    }

    if (tx == 0) {
        const int s = blockIdx.y;
#pragma unroll
        for (int t = 0; t < 8; t++) {
            const int tok = mbase + ty * 8 + t;
            g_pval[tok * SPLIT + s] = bv[t];
            g_pidx[tok * SPLIT + s] = bi[t];
        }
    }
}

// ---------------- combine split partials + gather ----------------
__global__ void reduce_gather_kernel(const float* __restrict__ wt, float* __restrict__ out) {
    const int tok = blockIdx.x;
    float bv = -3.402823e38f;
    int   bi = 0x7fffffff;
#pragma unroll
    for (int s = 0; s < SPLIT; s++) {
        const float v = g_pval[tok * SPLIT + s];
        const int   i = g_pidx[tok * SPLIT + s];
        if (v > bv || (v == bv && i < bi)) { bv = v; bi = i; }
    }
    const float4 v = *(const float4*)(wt + (size_t)bi * DIM + threadIdx.x * 4);
    *(float4*)(out + (size_t)tok * DIM + threadIdx.x * 4) = v;
}

// ---------------- launch ----------------
extern "C" void kernel_launch(void* const* d_in, const int* in_sizes, int n_in,
                              void* d_out, int out_size) {
    const float* x  = (const float*)d_in[0];   // [16384, 256]
    const float* wt = (const float*)d_in[1];   // [8192, 256]
    float* out = (float*)d_out;

    cudaFuncSetAttribute(vq_ffma_kernel, cudaFuncAttributeMaxDynamicSharedMemorySize, SMEM_BYTES);

    {
        float* xT2 = 0; float* wT = 0;
        cudaGetSymbolAddress((void**)&xT2, g_xT2);
        cudaGetSymbolAddress((void**)&wT, g_wT);
        dim3 bt(32, 8);
        dup_transpose_kernel<<<dim3(DIM / 32, TOKENS / 32), bt>>>(x, xT2);
        transpose_kernel<<<dim3(DIM / 32, KW / 32), bt>>>(wt, wT, KW);
        wnorm_kernel<<<KW / 256, 256>>>(wt);
    }

    dim3 grid(TOKENS / BM, SPLIT);
    vq_ffma_kernel<<<grid, 256, SMEM_BYTES>>>();

    reduce_gather_kernel<<<TOKENS, 64>>>(wt, out);
}